// round 4
// baseline (speedup 1.0000x reference)
#include <cuda_runtime.h>
#include <cstdint>

// GaussianVoxel fused, z-amortized: all 4 levels [16,17,zr,64,64]
// (zr in {1,2,4,64}) in ONE launch. Z_COEFFS=(1,1,1,13), PAD=6, PATCH=13.
//
// Level 3 (90% of bytes): each thread writes 4 z-slices of one (bj,y,x4)
// float4 — decode/coords once, 4 independent lane-contiguous STG.128.
// Levels 0-2: one float4 per thread (as R3).
// Pure store-bound: ~316 MB streaming stores, inputs L1-resident.

#define BATCH 16
#define JOINTS 17
#define NBJ (BATCH * JOINTS)   // 272
#define SIZE 64
#define PADC 6
#define PATCH 13

// per-level thread counts
#define F0 (NBJ * 1  * SIZE * (SIZE / 4))        // 278528  (1 float4/thread)
#define F1 (NBJ * 2  * SIZE * (SIZE / 4))        // 557056
#define F2 (NBJ * 4  * SIZE * (SIZE / 4))        // 1114112
#define F3 (NBJ * 16 * SIZE * (SIZE / 4))        // 4456448 (4 float4/thread, 4 z each)
#define C0 (F0)            // 278528
#define C1 (C0 + F1)       // 835584
#define C2 (C1 + F2)       // 1949696
#define TOT (C2 + F3)      // 6406144 = 25024 * 256 exactly

// float4 offsets of levels in flat output
#define O1 C0
#define O2 C1
#define O3 C2              // level3 starts at float4 index 1949696

template<int ZRES>
__device__ __forceinline__ void do_small(int lidx,
                                         const float* __restrict__ coords,
                                         const float* __restrict__ g,
                                         float4* __restrict__ out)
{
    // lidx = ((bj*ZRES + z)*64 + y)*16 + x4 ; ZC = 1 for levels 0-2
    int x4 = lidx & 15;
    int t  = lidx >> 4;
    int y  = t & 63;
    t >>= 6;
    int z, bj;
    if (ZRES == 1) { z = 0; bj = t; }
    else           { z = t & (ZRES - 1); bj = t >> (ZRES == 2 ? 1 : 2); }

    float cx = __ldg(&coords[bj * 3 + 0]);
    float cy = __ldg(&coords[bj * 3 + 1]);
    float cz = __ldg(&coords[bj * 3 + 2]);
    int xi = (int)cx;
    int yi = (int)cy;
    int zidx = (int)ceilf(cz * ((float)ZRES * (1.0f / 64.0f))) - 1;

    int gz = z - zidx;            // ZC=1, ZPAD=0: valid iff gz==0
    int gy = y - yi + PADC;

    float4 v = make_float4(0.f, 0.f, 0.f, 0.f);
    if (gz == 0 && (unsigned)gy < (unsigned)PATCH) {
        const float* gp = g + gy * PATCH;
        int x0 = x4 * 4;
        float r[4];
        #pragma unroll
        for (int k = 0; k < 4; k++) {
            int gx = x0 + k - xi + PADC;
            r[k] = ((unsigned)gx < (unsigned)PATCH) ? __ldg(&gp[gx]) : 0.f;
        }
        v = make_float4(r[0], r[1], r[2], r[3]);
    }
    __stcs(&out[lidx], v);
}

__device__ __forceinline__ void do_level3(int lidx,
                                          const float* __restrict__ coords,
                                          const float* __restrict__ g,
                                          float4* __restrict__ out)
{
    // lidx = ((bj*16 + z4)*64 + y)*16 + x4 ; thread covers z = z4*4 .. z4*4+3
    int x4 = lidx & 15;
    int t  = lidx >> 4;
    int y  = t & 63;
    t >>= 6;
    int z4 = t & 15;
    int bj = t >> 4;

    float cx = __ldg(&coords[bj * 3 + 0]);
    float cy = __ldg(&coords[bj * 3 + 1]);
    float cz = __ldg(&coords[bj * 3 + 2]);
    int xi = (int)cx;
    int yi = (int)cy;
    int zidx = (int)cz;           // ZRES=64: ceil(cz*64/64)-1 = cz-1... careful
    // zidx = ceil(cz) - 1 = cz - 1 for integer-valued cz>=1; cz=0 -> -1.
    zidx = (int)ceilf(cz) - 1;

    int zbase = z4 * 4;
    int gy = y - yi + PADC;

    float4 v[4];
    #pragma unroll
    for (int i = 0; i < 4; i++) v[i] = make_float4(0.f, 0.f, 0.f, 0.f);

    if ((unsigned)gy < (unsigned)PATCH) {
        int x0 = x4 * 4;
        #pragma unroll
        for (int i = 0; i < 4; i++) {
            int gz = zbase + i - zidx + 6;        // ZC=13, ZPAD=6
            if ((unsigned)gz < 13u) {
                const float* gp = g + (gz * PATCH + gy) * PATCH;
                float r[4];
                #pragma unroll
                for (int k = 0; k < 4; k++) {
                    int gx = x0 + k - xi + PADC;
                    r[k] = ((unsigned)gx < (unsigned)PATCH) ? __ldg(&gp[gx]) : 0.f;
                }
                v[i] = make_float4(r[0], r[1], r[2], r[3]);
            }
        }
    }

    // float4 index of (bj, zbase, y, x4); consecutive z = +1024 float4
    int base = ((bj * 64 + zbase) * 64 + y) * 16 + x4;
    #pragma unroll
    for (int i = 0; i < 4; i++)
        __stcs(&out[base + i * 1024], v[i]);
}

__global__ __launch_bounds__(256)
void gv_fused_kernel(const float* __restrict__ coords,
                     const float* __restrict__ g0,
                     const float* __restrict__ g1,
                     const float* __restrict__ g2,
                     const float* __restrict__ g3,
                     float4* __restrict__ out)
{
    int idx = blockIdx.x * blockDim.x + threadIdx.x;  // exact grid, no bounds check

    if (idx >= C2) {
        do_level3(idx - C2, coords, g3, out + O3);
    } else if (idx < C0) {
        do_small<1>(idx, coords, g0, out);
    } else if (idx < C1) {
        do_small<2>(idx - C0, coords, g1, out + O1);
    } else {
        do_small<4>(idx - C1, coords, g2, out + O2);
    }
}

extern "C" void kernel_launch(void* const* d_in, const int* in_sizes, int n_in,
                              void* d_out, int out_size)
{
    const float* coords = (const float*)d_in[0];
    const float* g0 = (const float*)d_in[1];
    const float* g1 = (const float*)d_in[2];
    const float* g2 = (const float*)d_in[3];
    const float* g3 = (const float*)d_in[4];

    gv_fused_kernel<<<TOT / 256, 256>>>(coords, g0, g1, g2, g3, (float4*)d_out);
}

// round 6
// speedup vs baseline: 1.0506x; 1.0506x over previous
#include <cuda_runtime.h>
#include <cstdint>

// GaussianVoxel fused, STG.256: all 4 levels [16,17,zr,64,64] (zr in
// {1,2,4,64}) in ONE launch. Z_COEFFS=(1,1,1,13), PAD=6, PATCH=13.
//
// One thread = 8 consecutive floats = one 256-bit streaming store.
// A warp's single st.global.cs.v8 covers 1024B contiguous (8 full lines).
// ~316 MB stores; inputs L1-resident. 32B-unit store index == thread index.

#define BATCH 16
#define JOINTS 17
#define NBJ (BATCH * JOINTS)   // 272
#define SIZE 64
#define PADC 6
#define PATCH 13

// per-level thread counts (8 floats / thread)
#define T0 (NBJ * 1  * SIZE * (SIZE / 8))   // 139264
#define T1 (NBJ * 2  * SIZE * (SIZE / 8))   // 278528
#define T2 (NBJ * 4  * SIZE * (SIZE / 8))   // 557056
#define T3 (NBJ * 64 * SIZE * (SIZE / 8))   // 8912896
#define C0 (T0)            // 139264
#define C1 (C0 + T1)       // 417792
#define C2 (C1 + T2)       // 974848
#define TOT (C2 + T3)      // 9887744 = 38624 * 256 exactly

struct alignas(32) f8 { float v[8]; };

__device__ __forceinline__ void st256cs(f8* p, const uint32_t r[8])
{
    asm volatile("st.global.cs.v8.b32 [%0], {%1,%2,%3,%4,%5,%6,%7,%8};"
                 :: "l"(p),
                    "r"(r[0]), "r"(r[1]), "r"(r[2]), "r"(r[3]),
                    "r"(r[4]), "r"(r[5]), "r"(r[6]), "r"(r[7])
                 : "memory");
}

template<int ZRES, int ZC>
__device__ __forceinline__ void do_level(int lidx,
                                         const float* __restrict__ coords,
                                         const float* __restrict__ g,
                                         f8* __restrict__ out)
{
    // lidx = ((bj*ZRES + z)*64 + y)*8 + x8
    int x8 = lidx & 7;
    int t  = lidx >> 3;
    int y  = t & 63;
    t >>= 6;
    int z, bj;
    if (ZRES == 1) { z = 0; bj = t; }
    else           { z = t & (ZRES - 1);
                     bj = t >> (ZRES == 2 ? 1 : (ZRES == 4 ? 2 : 6)); }

    // coords table: 3.3 KB, L1-resident
    float cx = __ldg(&coords[bj * 3 + 0]);
    float cy = __ldg(&coords[bj * 3 + 1]);
    float cz = __ldg(&coords[bj * 3 + 2]);
    int xi = (int)cx;
    int yi = (int)cy;
    // zidx = ceil(cz * ZRES / 64) - 1  (cz integer-valued 0..63, exact in fp32)
    int zidx = (int)ceilf(cz * ((float)ZRES * (1.0f / 64.0f))) - 1;

    constexpr int ZPAD = ZC / 2;
    int gz = z - zidx + ZPAD;
    int gy = y - yi + PADC;

    uint32_t r[8];
    #pragma unroll
    for (int k = 0; k < 8; k++) r[k] = 0u;

    if ((unsigned)gz < (unsigned)ZC && (unsigned)gy < (unsigned)PATCH) {
        const float* gp = g + (gz * PATCH + gy) * PATCH;
        int x0 = x8 * 8;
        #pragma unroll
        for (int k = 0; k < 8; k++) {
            int gx = x0 + k - xi + PADC;
            if ((unsigned)gx < (unsigned)PATCH)
                r[k] = __float_as_uint(__ldg(&gp[gx]));
        }
    }
    st256cs(&out[lidx], r);
}

__global__ __launch_bounds__(256)
void gv_fused_kernel(const float* __restrict__ coords,
                     const float* __restrict__ g0,
                     const float* __restrict__ g1,
                     const float* __restrict__ g2,
                     const float* __restrict__ g3,
                     f8* __restrict__ out)
{
    int idx = blockIdx.x * blockDim.x + threadIdx.x;  // exact grid, no bounds check

    // 32B-unit level offsets equal the cumulative thread counts
    if (idx >= C2) {
        do_level<64, 13>(idx - C2, coords, g3, out + C2);
    } else if (idx < C0) {
        do_level<1, 1>(idx, coords, g0, out);
    } else if (idx < C1) {
        do_level<2, 1>(idx - C0, coords, g1, out + C0);
    } else {
        do_level<4, 1>(idx - C1, coords, g2, out + C1);
    }
}

extern "C" void kernel_launch(void* const* d_in, const int* in_sizes, int n_in,
                              void* d_out, int out_size)
{
    const float* coords = (const float*)d_in[0];
    const float* g0 = (const float*)d_in[1];
    const float* g1 = (const float*)d_in[2];
    const float* g2 = (const float*)d_in[3];
    const float* g3 = (const float*)d_in[4];

    gv_fused_kernel<<<TOT / 256, 256>>>(coords, g0, g1, g2, g3, (f8*)d_out);
}